// round 4
// baseline (speedup 1.0000x reference)
#include <cuda_runtime.h>
#include <cuda_bf16.h>

// Problem constants
#define B_    16
#define CIN_  64
#define COUT_ 64
#define H_    130
#define W_    130
#define HO_   128
#define WO_   128
#define G_    8
#define CPG_  8
#define SP_   (HO_*WO_)      // 16384
#define OFFC_ (G_*2*9)       // 144
#define YSIZE_ ((size_t)B_*COUT_*SP_)   // 16777216

// Scratch (no allocation allowed -> device globals)
__device__ float g_t1[(size_t)B_*CIN_*SP_];    // conv1 output, 67MB
__device__ float g_w1t[CIN_*9*CIN_];           // [ci][tap][co]
__device__ float g_w2t[CIN_*OFFC_];            // [ci][oc]
__device__ float g_wdt[CIN_*9*COUT_];          // [k=cin*9+tap][co]

// ---------------------------------------------------------------------------
// Prep: transpose weights once so all later smem fills are coalesced.
// ---------------------------------------------------------------------------
__global__ void prep_kernel(const float* __restrict__ w1,
                            const float* __restrict__ w2,
                            const float* __restrict__ wd) {
    int idx = blockIdx.x * 256 + threadIdx.x;
    if (idx < 36864) {                       // w1t[ci][tap][co]
        int co = idx & 63;
        int rest = idx >> 6;
        int tap = rest % 9;
        int ci  = rest / 9;
        g_w1t[idx] = w1[co*576 + ci*9 + tap];
    }
    int j2 = idx - 36864;
    if (j2 >= 0 && j2 < 9216) {              // w2t[ci][oc]
        int oc = j2 % 144;
        int ci = j2 / 144;
        g_w2t[j2] = w2[oc*64 + ci];
    }
    int j3 = idx - 46080;
    if (j3 >= 0 && j3 < 36864) {             // wdt[k][co]
        int co = j3 & 63;
        int k  = j3 >> 6;
        g_wdt[j3] = wd[co*576 + k];
    }
}

// ---------------------------------------------------------------------------
// conv1: 3x3 VALID, 64->64.  Block: 16x16 pixels x 16 couts. cin chunks of 8.
// ---------------------------------------------------------------------------
__global__ __launch_bounds__(256) void conv1_kernel(const float* __restrict__ x,
                                                    const float* __restrict__ b1) {
    __shared__ __align__(16) float xs[8][18][18];
    __shared__ __align__(16) float ws[8][9][16];   // [ci][tap][cc]

    int tid = threadIdx.x;
    int tx = tid & 15, ty = tid >> 4;
    int c0 = blockIdx.x * 16;
    int r0 = blockIdx.y * 16;
    int bz = blockIdx.z;            // b*4 + cog
    int b  = bz >> 2, cog = bz & 3;

    float acc[16];
#pragma unroll
    for (int i = 0; i < 16; ++i) acc[i] = 0.f;

    for (int ch = 0; ch < 8; ++ch) {
        int ci0 = ch * 8;
        __syncthreads();
        // x tile: rows r0..r0+17, cols c0..c0+17, 8 channels
        for (int idx = tid; idx < 8*18*18; idx += 256) {
            int ci = idx / 324;
            int rem = idx - ci*324;
            int r = rem / 18;
            int c = rem - r*18;
            xs[ci][r][c] = x[(((size_t)b*64 + ci0+ci)*130 + (r0+r))*130 + (c0+c)];
        }
        // weights for this chunk, cc-contiguous (coalesced from g_w1t)
        for (int idx = tid; idx < 1152; idx += 256) {
            int cc = idx & 15;
            int rest = idx >> 4;
            int tap = rest % 9;
            int ci  = rest / 9;
            ws[ci][tap][cc] = g_w1t[(ci0+ci)*576 + tap*64 + cog*16 + cc];
        }
        __syncthreads();

#pragma unroll
        for (int ci = 0; ci < 8; ++ci) {
            float xv[9];
#pragma unroll
            for (int di = 0; di < 3; ++di)
#pragma unroll
                for (int dj = 0; dj < 3; ++dj)
                    xv[di*3+dj] = xs[ci][ty+di][tx+dj];
#pragma unroll
            for (int tap = 0; tap < 9; ++tap) {
                const float4* wp = (const float4*)&ws[ci][tap][0];
                float4 wA = wp[0], wB = wp[1], wC = wp[2], wD = wp[3];
                float v = xv[tap];
                acc[0]  += v*wA.x; acc[1]  += v*wA.y; acc[2]  += v*wA.z; acc[3]  += v*wA.w;
                acc[4]  += v*wB.x; acc[5]  += v*wB.y; acc[6]  += v*wB.z; acc[7]  += v*wB.w;
                acc[8]  += v*wC.x; acc[9]  += v*wC.y; acc[10] += v*wC.z; acc[11] += v*wC.w;
                acc[12] += v*wD.x; acc[13] += v*wD.y; acc[14] += v*wD.z; acc[15] += v*wD.w;
            }
        }
    }
#pragma unroll
    for (int cc = 0; cc < 16; ++cc) {
        int co = cog*16 + cc;
        g_t1[(((size_t)b*64 + co) << 14) + (r0+ty)*128 + (c0+tx)] = acc[cc] + __ldg(&b1[co]);
    }
}

// ---------------------------------------------------------------------------
// conv2: 1x1, 64->144 (offsets). Block: 64 pixels x 144 oc. t1 read once.
// ---------------------------------------------------------------------------
__global__ __launch_bounds__(256) void conv2_kernel(const float* __restrict__ b2,
                                                    float* __restrict__ out_off) {
    __shared__ __align__(16) float w2s[64*144];   // [ci][oc]  36.9KB
    __shared__ __align__(16) float ts[16][64];    // [ci][pix]

    int tid = threadIdx.x;
    int pix = tid & 63, ocg = tid >> 6;           // ocg 0..3
    int p0 = blockIdx.x * 64;
    int b  = p0 >> 14;
    int sp = p0 & 16383;

    for (int idx = tid; idx < 9216; idx += 256) w2s[idx] = g_w2t[idx];

    float acc[36];
#pragma unroll
    for (int i = 0; i < 36; ++i) acc[i] = 0.f;

    const float* t1b = g_t1 + (size_t)b*64*16384 + sp;

    for (int ch = 0; ch < 4; ++ch) {
        __syncthreads();
        for (int idx = tid; idx < 1024; idx += 256) {
            int ci = idx >> 6, pp = idx & 63;
            ts[ci][pp] = t1b[(ch*16 + ci)*16384 + pp];
        }
        __syncthreads();
#pragma unroll
        for (int ci = 0; ci < 16; ++ci) {
            float xv = ts[ci][pix];
            const float4* wp = (const float4*)&w2s[(ch*16 + ci)*144];
#pragma unroll
            for (int m = 0; m < 9; ++m) {
                float4 w = wp[ocg + m*4];         // oc = ocg*4 + m*16 + {0..3}
                acc[m*4+0] += xv*w.x; acc[m*4+1] += xv*w.y;
                acc[m*4+2] += xv*w.z; acc[m*4+3] += xv*w.w;
            }
        }
    }
    float* ob = out_off + (size_t)b*144*16384 + sp + pix;
#pragma unroll
    for (int m = 0; m < 9; ++m)
#pragma unroll
        for (int l = 0; l < 4; ++l) {
            int oc = ocg*4 + m*16 + l;
            ob[(size_t)oc*16384] = acc[m*4+l] + __ldg(&b2[oc]);
        }
}

// ---------------------------------------------------------------------------
// deform conv: phase 1 builds the interpolated 576-vector per pixel (shared
// by all 64 couts) into smem; phase 2 is a smem GEMM [64x576]x[576x16].
// Block: 16 pixels of one output row, one batch. 44.9KB static smem (<48KB,
// no cudaFuncSetAttribute needed).
// ---------------------------------------------------------------------------
__global__ __launch_bounds__(256) void deform_kernel(const float* __restrict__ x,
                                                     const float* __restrict__ off,
                                                     float* __restrict__ yout) {
    __shared__ __align__(16) float v_s[576 * 16];   // [k][pix]  36.9KB
    __shared__ __align__(16) float wd_s[32 * 64];   // [kk][co]  8KB

    int tid = threadIdx.x;
    int b   = blockIdx.z;
    int ho  = blockIdx.y;
    int wo0 = blockIdx.x * 16;

    // ---- Phase 1: gather + bilinear. 72 (g,tap) x 16 pix = 1152 tasks.
    for (int taskid = tid; taskid < 1152; taskid += 256) {
        int pix = taskid & 15;
        int gt  = taskid >> 4;            // mostly uniform within a warp
        int g   = gt / 9;
        int tap = gt - g*9;
        int i   = tap / 3;
        int j   = tap - i*3;
        int wo  = wo0 + pix;

        size_t ob = ((size_t)(b*144 + (g*9 + tap)*2))*16384 + (size_t)ho*128 + wo;
        float dy = off[ob];
        float dx = off[ob + 16384];
        float py = dy + (float)(ho + i);
        float px = dx + (float)(wo + j);
        float y0f = floorf(py), x0f = floorf(px);
        float ly = py - y0f, lx = px - x0f;
        int y0 = (int)y0f, x0 = (int)x0f;
        int y1 = y0 + 1,  x1 = x0 + 1;

        float my0 = (y0 >= 0 && y0 < 130) ? 1.f : 0.f;
        float my1 = (y1 >= 0 && y1 < 130) ? 1.f : 0.f;
        float mx0 = (x0 >= 0 && x0 < 130) ? 1.f : 0.f;
        float mx1 = (x1 >= 0 && x1 < 130) ? 1.f : 0.f;

        int yc0 = min(max(y0, 0), 129), yc1 = min(max(y1, 0), 129);
        int xc0 = min(max(x0, 0), 129), xc1 = min(max(x1, 0), 129);

        float a00 = (1.f-ly)*(1.f-lx)*my0*mx0;
        float a01 = (1.f-ly)*lx      *my0*mx1;
        float a10 = ly      *(1.f-lx)*my1*mx0;
        float a11 = ly      *lx      *my1*mx1;

        int i00 = yc0*130 + xc0, i01 = yc0*130 + xc1;
        int i10 = yc1*130 + xc0, i11 = yc1*130 + xc1;

        const float* xb = x + ((size_t)b*64 + g*8)*16900;
        int kbase = (g*8)*9 + tap;
#pragma unroll
        for (int c = 0; c < 8; ++c) {
            const float* xc = xb + c*16900;
            float v = a00*xc[i00] + a01*xc[i01] + a10*xc[i10] + a11*xc[i11];
            v_s[(kbase + c*9)*16 + pix] = v;
        }
    }
    __syncthreads();

    // ---- Phase 2: y[co][pix] = sum_k v_s[k][pix] * wdt[k][co]
    // 256 threads = 16 pixels x 16 cout-groups (4 couts each).
    int pix = tid & 15, cg = tid >> 4;    // cg 0..15 -> couts cg*4..cg*4+3
    float acc[4] = {0.f, 0.f, 0.f, 0.f};

    for (int kc = 0; kc < 18; ++kc) {     // 18 chunks of 32 k
        if (kc) __syncthreads();
        for (int idx = tid; idx < 2048; idx += 256)
            wd_s[idx] = g_wdt[kc*2048 + idx];     // straight coalesced copy
        __syncthreads();
#pragma unroll
        for (int kk = 0; kk < 32; ++kk) {
            float xv = v_s[(kc*32 + kk)*16 + pix];
            const float4* wp = (const float4*)&wd_s[kk*64 + cg*4];
            float4 wa = wp[0];
            acc[0] += xv*wa.x; acc[1] += xv*wa.y;
            acc[2] += xv*wa.z; acc[3] += xv*wa.w;
        }
    }

    float* yb = yout + ((size_t)b*64 + cg*4)*16384 + (size_t)ho*128 + wo0 + pix;
#pragma unroll
    for (int q = 0; q < 4; ++q) yb[(size_t)q*16384] = acc[q];
}

// ---------------------------------------------------------------------------
extern "C" void kernel_launch(void* const* d_in, const int* in_sizes, int n_in,
                              void* d_out, int out_size) {
    const float* x  = (const float*)d_in[0];
    const float* w1 = (const float*)d_in[1];
    const float* b1 = (const float*)d_in[2];
    const float* w2 = (const float*)d_in[3];
    const float* b2 = (const float*)d_in[4];
    const float* wd = (const float*)d_in[5];

    float* out    = (float*)d_out;
    float* yout   = out;              // y:  [16,64,128,128]
    float* offout = out + YSIZE_;     // off:[16,144,128,128]

    prep_kernel<<<324, 256>>>(w1, w2, wd);
    conv1_kernel<<<dim3(8, 8, 64), 256>>>(x, b1);
    conv2_kernel<<<4096, 256>>>(b2, offout);
    deform_kernel<<<dim3(8, 128, 16), 256>>>(x, offout, yout);
}

// round 9
// speedup vs baseline: 1.1188x; 1.1188x over previous
#include <cuda_runtime.h>
#include <cuda_bf16.h>

// Problem constants
#define B_    16
#define CIN_  64
#define COUT_ 64
#define H_    130
#define W_    130
#define HO_   128
#define WO_   128
#define G_    8
#define CPG_  8
#define SP_   (HO_*WO_)      // 16384
#define OFFC_ (G_*2*9)       // 144
#define YSIZE_ ((size_t)B_*COUT_*SP_)   // 16777216

typedef unsigned long long u64;

// Packed f32x2 helpers (FFMA2 — ptxas never emits this from C++)
__device__ __forceinline__ u64 pack2(float a, float b) {
    u64 r;
    asm("mov.b64 %0, {%1, %2};" : "=l"(r)
        : "r"(__float_as_uint(a)), "r"(__float_as_uint(b)));
    return r;
}
__device__ __forceinline__ void fma2(u64& d, u64 a, u64 b) {
    asm("fma.rn.f32x2 %0, %1, %2, %0;" : "+l"(d) : "l"(a), "l"(b));
}
__device__ __forceinline__ float lo32(u64 v) { return __uint_as_float((unsigned)v); }
__device__ __forceinline__ float hi32(u64 v) { return __uint_as_float((unsigned)(v >> 32)); }

// Scratch (no allocation allowed -> device globals)
__device__ float g_t1[(size_t)B_*CIN_*SP_];    // conv1 output, 67MB
__device__ float g_w1t[CIN_*9*CIN_];           // [ci][tap][co]
__device__ float g_w2t[CIN_*OFFC_];            // [ci][oc]
__device__ float g_wdt[CIN_*9*COUT_];          // [k=cin*9+tap][co]

// ---------------------------------------------------------------------------
// Prep: transpose weights once so all later smem fills are coalesced.
// ---------------------------------------------------------------------------
__global__ void prep_kernel(const float* __restrict__ w1,
                            const float* __restrict__ w2,
                            const float* __restrict__ wd) {
    int idx = blockIdx.x * 256 + threadIdx.x;
    if (idx < 36864) {                       // w1t[ci][tap][co]
        int co = idx & 63;
        int rest = idx >> 6;
        int tap = rest % 9;
        int ci  = rest / 9;
        g_w1t[idx] = w1[co*576 + ci*9 + tap];
    }
    int j2 = idx - 36864;
    if (j2 >= 0 && j2 < 9216) {              // w2t[ci][oc]
        int oc = j2 % 144;
        int ci = j2 / 144;
        g_w2t[j2] = w2[oc*64 + ci];
    }
    int j3 = idx - 46080;
    if (j3 >= 0 && j3 < 36864) {             // wdt[k][co]
        int co = j3 & 63;
        int k  = j3 >> 6;
        g_wdt[j3] = wd[co*576 + k];
    }
}

// ---------------------------------------------------------------------------
// conv1: 3x3 VALID, 64->64.  Block: 32x16 pixel tile x 16 couts.
// Each thread: 2 pixels (cols tx and tx+16) x 16 couts, f32x2 accumulators
// paired over couts. cin chunks of 8.
// ---------------------------------------------------------------------------
__global__ __launch_bounds__(256) void conv1_kernel(const float* __restrict__ x,
                                                    const float* __restrict__ b1) {
    __shared__ __align__(16) float xs[8][18][34];  // 19.1KB
    __shared__ __align__(16) float ws[8][9][16];   // [ci][tap][cc] 4.6KB

    int tid = threadIdx.x;
    int tx = tid & 15, ty = tid >> 4;       // ty 0..15
    int c0 = blockIdx.x * 32;
    int r0 = blockIdx.y * 16;
    int bz = blockIdx.z;                    // b*4 + cog
    int b  = bz >> 2, cog = bz & 3;

    u64 accA[8], accB[8];                   // pixel A (tx), pixel B (tx+16); pairs over couts
#pragma unroll
    for (int i = 0; i < 8; ++i) { accA[i] = 0ull; accB[i] = 0ull; }

    for (int ch = 0; ch < 8; ++ch) {
        int ci0 = ch * 8;
        __syncthreads();
        // x tile: rows r0..r0+17, cols c0..c0+33, 8 channels
        for (int idx = tid; idx < 8*18*34; idx += 256) {
            int ci = idx / 612;
            int rem = idx - ci*612;
            int r = rem / 34;
            int c = rem - r*34;
            xs[ci][r][c] = x[(((size_t)b*64 + ci0+ci)*130 + (r0+r))*130 + (c0+c)];
        }
        // weights for this chunk, cc-contiguous (coalesced from g_w1t)
        for (int idx = tid; idx < 1152; idx += 256) {
            int cc = idx & 15;
            int rest = idx >> 4;
            int tap = rest % 9;
            int ci  = rest / 9;
            ws[ci][tap][cc] = g_w1t[(ci0+ci)*576 + tap*64 + cog*16 + cc];
        }
        __syncthreads();

#pragma unroll
        for (int ci = 0; ci < 8; ++ci) {
            float xvA[9], xvB[9];
#pragma unroll
            for (int di = 0; di < 3; ++di)
#pragma unroll
                for (int dj = 0; dj < 3; ++dj) {
                    xvA[di*3+dj] = xs[ci][ty+di][tx+dj];
                    xvB[di*3+dj] = xs[ci][ty+di][tx+16+dj];
                }
#pragma unroll
            for (int tap = 0; tap < 9; ++tap) {
                const ulonglong2* wp = (const ulonglong2*)&ws[ci][tap][0];
                ulonglong2 w01 = wp[0], w23 = wp[1], w45 = wp[2], w67 = wp[3];
                u64 vA = pack2(xvA[tap], xvA[tap]);
                u64 vB = pack2(xvB[tap], xvB[tap]);
                fma2(accA[0], vA, w01.x); fma2(accA[1], vA, w01.y);
                fma2(accA[2], vA, w23.x); fma2(accA[3], vA, w23.y);
                fma2(accA[4], vA, w45.x); fma2(accA[5], vA, w45.y);
                fma2(accA[6], vA, w67.x); fma2(accA[7], vA, w67.y);
                fma2(accB[0], vB, w01.x); fma2(accB[1], vB, w01.y);
                fma2(accB[2], vB, w23.x); fma2(accB[3], vB, w23.y);
                fma2(accB[4], vB, w45.x); fma2(accB[5], vB, w45.y);
                fma2(accB[6], vB, w67.x); fma2(accB[7], vB, w67.y);
            }
        }
    }
    size_t obase = ((size_t)b*64 + cog*16) << 14;
    int pA = (r0+ty)*128 + (c0+tx);
    int pB = pA + 16;
#pragma unroll
    for (int p = 0; p < 8; ++p) {
        float bl = __ldg(&b1[cog*16 + 2*p]);
        float bh = __ldg(&b1[cog*16 + 2*p + 1]);
        g_t1[obase + ((size_t)(2*p)   << 14) + pA] = lo32(accA[p]) + bl;
        g_t1[obase + ((size_t)(2*p+1) << 14) + pA] = hi32(accA[p]) + bh;
        g_t1[obase + ((size_t)(2*p)   << 14) + pB] = lo32(accB[p]) + bl;
        g_t1[obase + ((size_t)(2*p+1) << 14) + pB] = hi32(accB[p]) + bh;
    }
}

// ---------------------------------------------------------------------------
// conv2: 1x1, 64->144 (offsets). Block: 64 pixels x 144 oc. t1 read once.
// f32x2 accumulators paired over adjacent oc.
// ---------------------------------------------------------------------------
__global__ __launch_bounds__(256) void conv2_kernel(const float* __restrict__ b2,
                                                    float* __restrict__ out_off) {
    __shared__ __align__(16) float w2s[64*144];   // [ci][oc]  36.9KB
    __shared__ __align__(16) float ts[16][64];    // [ci][pix]

    int tid = threadIdx.x;
    int pix = tid & 63, ocg = tid >> 6;           // ocg 0..3
    int p0 = blockIdx.x * 64;
    int b  = p0 >> 14;
    int sp = p0 & 16383;

    for (int idx = tid; idx < 9216; idx += 256) w2s[idx] = g_w2t[idx];

    u64 acc[18];                                  // m=0..8, two oc-pairs each
#pragma unroll
    for (int i = 0; i < 18; ++i) acc[i] = 0ull;

    const float* t1b = g_t1 + (size_t)b*64*16384 + sp;

    for (int ch = 0; ch < 4; ++ch) {
        __syncthreads();
        for (int idx = tid; idx < 1024; idx += 256) {
            int ci = idx >> 6, pp = idx & 63;
            ts[ci][pp] = t1b[(ch*16 + ci)*16384 + pp];
        }
        __syncthreads();
#pragma unroll
        for (int ci = 0; ci < 16; ++ci) {
            float xv = ts[ci][pix];
            u64 xv2 = pack2(xv, xv);
            const ulonglong2* wp = (const ulonglong2*)&w2s[(ch*16 + ci)*144];
#pragma unroll
            for (int m = 0; m < 9; ++m) {
                ulonglong2 w = wp[ocg + m*4];     // oc = ocg*4 + m*16 + {0..3}
                fma2(acc[2*m],   xv2, w.x);
                fma2(acc[2*m+1], xv2, w.y);
            }
        }
    }
    float* ob = out_off + (size_t)b*144*16384 + sp + pix;
#pragma unroll
    for (int m = 0; m < 9; ++m) {
        int oc = ocg*4 + m*16;
        ob[(size_t)(oc  )*16384] = lo32(acc[2*m])   + __ldg(&b2[oc]);
        ob[(size_t)(oc+1)*16384] = hi32(acc[2*m])   + __ldg(&b2[oc+1]);
        ob[(size_t)(oc+2)*16384] = lo32(acc[2*m+1]) + __ldg(&b2[oc+2]);
        ob[(size_t)(oc+3)*16384] = hi32(acc[2*m+1]) + __ldg(&b2[oc+3]);
    }
}

// ---------------------------------------------------------------------------
// deform conv: phase 1 builds the interpolated 576-vector per pixel (shared
// by all 64 couts) into smem; phase 2 is a smem GEMM [64x576]x[576x16]
// with f32x2 accumulators. Block: 16 pixels of one output row, one batch.
// ---------------------------------------------------------------------------
__global__ __launch_bounds__(256) void deform_kernel(const float* __restrict__ x,
                                                     const float* __restrict__ off,
                                                     float* __restrict__ yout) {
    __shared__ __align__(16) float v_s[576 * 16];   // [k][pix]  36.9KB
    __shared__ __align__(16) float wd_s[32 * 64];   // [kk][co]  8KB

    int tid = threadIdx.x;
    int b   = blockIdx.z;
    int ho  = blockIdx.y;
    int wo0 = blockIdx.x * 16;

    // ---- Phase 1: gather + bilinear. 72 (g,tap) x 16 pix = 1152 tasks.
    for (int taskid = tid; taskid < 1152; taskid += 256) {
        int pix = taskid & 15;
        int gt  = taskid >> 4;
        int g   = gt / 9;
        int tap = gt - g*9;
        int i   = tap / 3;
        int j   = tap - i*3;
        int wo  = wo0 + pix;

        size_t ob = ((size_t)(b*144 + (g*9 + tap)*2))*16384 + (size_t)ho*128 + wo;
        float dy = off[ob];
        float dx = off[ob + 16384];
        float py = dy + (float)(ho + i);
        float px = dx + (float)(wo + j);
        float y0f = floorf(py), x0f = floorf(px);
        float ly = py - y0f, lx = px - x0f;
        int y0 = (int)y0f, x0 = (int)x0f;
        int y1 = y0 + 1,  x1 = x0 + 1;

        float my0 = (y0 >= 0 && y0 < 130) ? 1.f : 0.f;
        float my1 = (y1 >= 0 && y1 < 130) ? 1.f : 0.f;
        float mx0 = (x0 >= 0 && x0 < 130) ? 1.f : 0.f;
        float mx1 = (x1 >= 0 && x1 < 130) ? 1.f : 0.f;

        int yc0 = min(max(y0, 0), 129), yc1 = min(max(y1, 0), 129);
        int xc0 = min(max(x0, 0), 129), xc1 = min(max(x1, 0), 129);

        float a00 = (1.f-ly)*(1.f-lx)*my0*mx0;
        float a01 = (1.f-ly)*lx      *my0*mx1;
        float a10 = ly      *(1.f-lx)*my1*mx0;
        float a11 = ly      *lx      *my1*mx1;

        int i00 = yc0*130 + xc0, i01 = yc0*130 + xc1;
        int i10 = yc1*130 + xc0, i11 = yc1*130 + xc1;

        const float* xb = x + ((size_t)b*64 + g*8)*16900;
        int kbase = (g*8)*9 + tap;
#pragma unroll
        for (int c = 0; c < 8; ++c) {
            const float* xc = xb + c*16900;
            float v = a00*xc[i00] + a01*xc[i01] + a10*xc[i10] + a11*xc[i11];
            v_s[(kbase + c*9)*16 + pix] = v;
        }
    }
    __syncthreads();

    // ---- Phase 2: y[co][pix] = sum_k v_s[k][pix] * wdt[k][co]
    // 256 threads = 16 pixels x 16 cout-groups (4 couts each), f32x2 pairs.
    int pix = tid & 15, cg = tid >> 4;    // cg 0..15 -> couts cg*4..cg*4+3
    u64 acc0 = 0ull, acc1 = 0ull;

    for (int kc = 0; kc < 18; ++kc) {     // 18 chunks of 32 k
        if (kc) __syncthreads();
        for (int idx = tid; idx < 2048; idx += 256)
            wd_s[idx] = g_wdt[kc*2048 + idx];     // straight coalesced copy
        __syncthreads();
#pragma unroll
        for (int kk = 0; kk < 32; ++kk) {
            float xv = v_s[(kc*32 + kk)*16 + pix];
            u64 xv2 = pack2(xv, xv);
            ulonglong2 w = *(const ulonglong2*)&wd_s[kk*64 + cg*4];
            fma2(acc0, xv2, w.x);
            fma2(acc1, xv2, w.y);
        }
    }

    float* yb = yout + ((size_t)b*64 + cg*4)*16384 + (size_t)ho*128 + wo0 + pix;
    yb[0]                   = lo32(acc0);
    yb[(size_t)1*16384]     = hi32(acc0);
    yb[(size_t)2*16384]     = lo32(acc1);
    yb[(size_t)3*16384]     = hi32(acc1);
}

// ---------------------------------------------------------------------------
extern "C" void kernel_launch(void* const* d_in, const int* in_sizes, int n_in,
                              void* d_out, int out_size) {
    const float* x  = (const float*)d_in[0];
    const float* w1 = (const float*)d_in[1];
    const float* b1 = (const float*)d_in[2];
    const float* w2 = (const float*)d_in[3];
    const float* b2 = (const float*)d_in[4];
    const float* wd = (const float*)d_in[5];

    float* out    = (float*)d_out;
    float* yout   = out;              // y:  [16,64,128,128]
    float* offout = out + YSIZE_;     // off:[16,144,128,128]

    prep_kernel<<<324, 256>>>(w1, w2, wd);
    conv1_kernel<<<dim3(4, 8, 64), 256>>>(x, b1);
    conv2_kernel<<<4096, 256>>>(b2, offout);
    deform_kernel<<<dim3(8, 128, 16), 256>>>(x, offout, yout);
}

// round 12
// speedup vs baseline: 1.2815x; 1.1454x over previous
#include <cuda_runtime.h>
#include <cuda_bf16.h>

// Problem constants
#define B_    16
#define CIN_  64
#define COUT_ 64
#define H_    130
#define W_    130
#define HO_   128
#define WO_   128
#define G_    8
#define CPG_  8
#define SP_   (HO_*WO_)      // 16384
#define OFFC_ (G_*2*9)       // 144
#define YSIZE_ ((size_t)B_*COUT_*SP_)   // 16777216

typedef unsigned long long u64;

// Packed f32x2 helpers (FFMA2 — ptxas never emits this from C++)
__device__ __forceinline__ u64 pack2(float a, float b) {
    u64 r;
    asm("mov.b64 %0, {%1, %2};" : "=l"(r)
        : "r"(__float_as_uint(a)), "r"(__float_as_uint(b)));
    return r;
}
__device__ __forceinline__ void fma2(u64& d, u64 a, u64 b) {
    asm("fma.rn.f32x2 %0, %1, %2, %0;" : "+l"(d) : "l"(a), "l"(b));
}
__device__ __forceinline__ float lo32(u64 v) { return __uint_as_float((unsigned)v); }
__device__ __forceinline__ float hi32(u64 v) { return __uint_as_float((unsigned)(v >> 32)); }

// cp.async (LDGSTS) helpers — bypass L1 for bulk smem fills
__device__ __forceinline__ void cp16(float* s, const float* g) {
    unsigned sa = (unsigned)__cvta_generic_to_shared(s);
    asm volatile("cp.async.cg.shared.global [%0], [%1], 16;\n" :: "r"(sa), "l"(g));
}
#define CP_COMMIT() asm volatile("cp.async.commit_group;\n" ::: "memory")
#define CP_WAIT0()  asm volatile("cp.async.wait_group 0;\n" ::: "memory")

// Scratch (no allocation allowed -> device globals)
__device__ __align__(16) float g_t1[(size_t)B_*CIN_*SP_];    // conv1 output
__device__ __align__(16) float g_w1t[CIN_*9*CIN_];           // [ci][tap][co]
__device__ __align__(16) float g_w2t[CIN_*OFFC_];            // [ci][oc]
__device__ __align__(16) float g_wdt[CIN_*9*COUT_];          // [k=cin*9+tap][co]

// ---------------------------------------------------------------------------
// Prep: transpose weights once so all later smem fills are coalesced.
// ---------------------------------------------------------------------------
__global__ void prep_kernel(const float* __restrict__ w1,
                            const float* __restrict__ w2,
                            const float* __restrict__ wd) {
    int idx = blockIdx.x * 256 + threadIdx.x;
    if (idx < 36864) {                       // w1t[ci][tap][co]
        int co = idx & 63;
        int rest = idx >> 6;
        int tap = rest % 9;
        int ci  = rest / 9;
        g_w1t[idx] = w1[co*576 + ci*9 + tap];
    }
    int j2 = idx - 36864;
    if (j2 >= 0 && j2 < 9216) {              // w2t[ci][oc]
        int oc = j2 % 144;
        int ci = j2 / 144;
        g_w2t[j2] = w2[oc*64 + ci];
    }
    int j3 = idx - 46080;
    if (j3 >= 0 && j3 < 36864) {             // wdt[k][co]
        int co = j3 & 63;
        int k  = j3 >> 6;
        g_wdt[j3] = wd[co*576 + k];
    }
}

// ---------------------------------------------------------------------------
// conv1: 3x3 VALID, 64->64.  Block: 32x16 pixel tile x 16 couts.
// Each thread: 2 pixels x 16 couts, f32x2 accumulators. cin chunks of 8.
// (FFMA2-bound — unchanged from round 4.)
// ---------------------------------------------------------------------------
__global__ __launch_bounds__(256) void conv1_kernel(const float* __restrict__ x,
                                                    const float* __restrict__ b1) {
    __shared__ __align__(16) float xs[8][18][34];  // 19.1KB
    __shared__ __align__(16) float ws[8][9][16];   // [ci][tap][cc] 4.6KB

    int tid = threadIdx.x;
    int tx = tid & 15, ty = tid >> 4;       // ty 0..15
    int c0 = blockIdx.x * 32;
    int r0 = blockIdx.y * 16;
    int bz = blockIdx.z;                    // b*4 + cog
    int b  = bz >> 2, cog = bz & 3;

    u64 accA[8], accB[8];
#pragma unroll
    for (int i = 0; i < 8; ++i) { accA[i] = 0ull; accB[i] = 0ull; }

    for (int ch = 0; ch < 8; ++ch) {
        int ci0 = ch * 8;
        __syncthreads();
        for (int idx = tid; idx < 8*18*34; idx += 256) {
            int ci = idx / 612;
            int rem = idx - ci*612;
            int r = rem / 34;
            int c = rem - r*34;
            xs[ci][r][c] = x[(((size_t)b*64 + ci0+ci)*130 + (r0+r))*130 + (c0+c)];
        }
        for (int idx = tid; idx < 1152; idx += 256) {
            int cc = idx & 15;
            int rest = idx >> 4;
            int tap = rest % 9;
            int ci  = rest / 9;
            ws[ci][tap][cc] = g_w1t[(ci0+ci)*576 + tap*64 + cog*16 + cc];
        }
        __syncthreads();

#pragma unroll
        for (int ci = 0; ci < 8; ++ci) {
            float xvA[9], xvB[9];
#pragma unroll
            for (int di = 0; di < 3; ++di)
#pragma unroll
                for (int dj = 0; dj < 3; ++dj) {
                    xvA[di*3+dj] = xs[ci][ty+di][tx+dj];
                    xvB[di*3+dj] = xs[ci][ty+di][tx+16+dj];
                }
#pragma unroll
            for (int tap = 0; tap < 9; ++tap) {
                const ulonglong2* wp = (const ulonglong2*)&ws[ci][tap][0];
                ulonglong2 w01 = wp[0], w23 = wp[1], w45 = wp[2], w67 = wp[3];
                u64 vA = pack2(xvA[tap], xvA[tap]);
                u64 vB = pack2(xvB[tap], xvB[tap]);
                fma2(accA[0], vA, w01.x); fma2(accA[1], vA, w01.y);
                fma2(accA[2], vA, w23.x); fma2(accA[3], vA, w23.y);
                fma2(accA[4], vA, w45.x); fma2(accA[5], vA, w45.y);
                fma2(accA[6], vA, w67.x); fma2(accA[7], vA, w67.y);
                fma2(accB[0], vB, w01.x); fma2(accB[1], vB, w01.y);
                fma2(accB[2], vB, w23.x); fma2(accB[3], vB, w23.y);
                fma2(accB[4], vB, w45.x); fma2(accB[5], vB, w45.y);
                fma2(accB[6], vB, w67.x); fma2(accB[7], vB, w67.y);
            }
        }
    }
    size_t obase = ((size_t)b*64 + cog*16) << 14;
    int pA = (r0+ty)*128 + (c0+tx);
    int pB = pA + 16;
#pragma unroll
    for (int p = 0; p < 8; ++p) {
        float bl = __ldg(&b1[cog*16 + 2*p]);
        float bh = __ldg(&b1[cog*16 + 2*p + 1]);
        g_t1[obase + ((size_t)(2*p)   << 14) + pA] = lo32(accA[p]) + bl;
        g_t1[obase + ((size_t)(2*p+1) << 14) + pA] = hi32(accA[p]) + bh;
        g_t1[obase + ((size_t)(2*p)   << 14) + pB] = lo32(accB[p]) + bl;
        g_t1[obase + ((size_t)(2*p+1) << 14) + pB] = hi32(accB[p]) + bh;
    }
}

// ---------------------------------------------------------------------------
// conv2: 1x1, 64->144 (offsets). Block: 64 pixels x 144 oc.
// cp.async fills, double-buffered t1 tile.
// ---------------------------------------------------------------------------
__global__ __launch_bounds__(256) void conv2_kernel(const float* __restrict__ b2,
                                                    float* __restrict__ out_off) {
    __shared__ __align__(16) float w2s[64*144];    // [ci][oc]  36.9KB
    __shared__ __align__(16) float ts[2][16*64];   // [buf][ci*64+pix]  8KB

    int tid = threadIdx.x;
    int pix = tid & 63, ocg = tid >> 6;            // ocg 0..3
    int p0 = blockIdx.x * 64;
    int b  = p0 >> 14;
    int sp = p0 & 16383;

    const float* t1b = g_t1 + (size_t)b*64*16384 + sp;

    // prefetch weights + first t1 chunk
    for (int i = tid; i < 2304; i += 256) cp16(&w2s[i*4], &g_w2t[i*4]);
    {
        int ci = tid >> 4, q = (tid & 15) * 4;
        cp16(&ts[0][ci*64 + q], t1b + (size_t)ci*16384 + q);
    }
    CP_COMMIT();

    u64 acc[18];
#pragma unroll
    for (int i = 0; i < 18; ++i) acc[i] = 0ull;

    for (int ch = 0; ch < 4; ++ch) {
        CP_WAIT0();
        __syncthreads();
        if (ch < 3) {
            int ci = tid >> 4, q = (tid & 15) * 4;
            cp16(&ts[(ch+1) & 1][ci*64 + q],
                 t1b + (size_t)((ch+1)*16 + ci)*16384 + q);
            CP_COMMIT();
        }
        const float* tsc = ts[ch & 1];
#pragma unroll
        for (int ci = 0; ci < 16; ++ci) {
            float xv = tsc[ci*64 + pix];
            u64 xv2 = pack2(xv, xv);
            const ulonglong2* wp = (const ulonglong2*)&w2s[(ch*16 + ci)*144];
#pragma unroll
            for (int m = 0; m < 9; ++m) {
                ulonglong2 w = wp[ocg + m*4];      // oc = ocg*4 + m*16 + {0..3}
                fma2(acc[2*m],   xv2, w.x);
                fma2(acc[2*m+1], xv2, w.y);
            }
        }
        if (ch < 3) __syncthreads();
    }
    float* ob = out_off + (size_t)b*144*16384 + sp + pix;
#pragma unroll
    for (int m = 0; m < 9; ++m) {
        int oc = ocg*4 + m*16;
        ob[(size_t)(oc  )*16384] = lo32(acc[2*m])   + __ldg(&b2[oc]);
        ob[(size_t)(oc+1)*16384] = hi32(acc[2*m])   + __ldg(&b2[oc+1]);
        ob[(size_t)(oc+2)*16384] = lo32(acc[2*m+1]) + __ldg(&b2[oc+2]);
        ob[(size_t)(oc+3)*16384] = hi32(acc[2*m+1]) + __ldg(&b2[oc+3]);
    }
}

// ---------------------------------------------------------------------------
// deform conv: phase 1 builds interpolated 576-vector per pixel into smem;
// phase 2 is a smem GEMM [64x576]x[576x32]. Block: 32 pixels of one row.
// Weights double-buffered via cp.async (first chunk prefetched before phase1).
// Dynamic smem: 576*32*4 + 2*64*64*4 = 106496 B.
// ---------------------------------------------------------------------------
__global__ __launch_bounds__(256) void deform_kernel(const float* __restrict__ x,
                                                     const float* __restrict__ off,
                                                     float* __restrict__ yout) {
    extern __shared__ __align__(16) float sm[];
    float* v_s  = sm;                 // [k=0..575][pix=0..31]   73.7KB
    float* wd_s = sm + 576*32;        // 2 x [kk=0..63][co=0..63] 32KB

    int tid = threadIdx.x;
    int b   = blockIdx.z;
    int ho  = blockIdx.y;
    int wo0 = blockIdx.x * 32;

    // Prefetch weight chunk 0 while phase 1 runs
    for (int i = tid; i < 1024; i += 256) cp16(wd_s + i*4, g_wdt + i*4);
    CP_COMMIT();

    // ---- Phase 1: gather + bilinear. 72 (g,tap) x 32 pix = 2304 tasks.
#pragma unroll
    for (int t = 0; t < 9; ++t) {
        int taskid = t*256 + tid;
        int pix = taskid & 31;            // full warp = 32 pixels of one gt
        int gt  = taskid >> 5;
        int g   = gt / 9;
        int tap = gt - g*9;
        int i   = tap / 3;
        int j   = tap - i*3;
        int wo  = wo0 + pix;

        size_t ob = ((size_t)(b*144 + (g*9 + tap)*2))*16384 + (size_t)ho*128 + wo;
        float dy = off[ob];
        float dx = off[ob + 16384];
        float py = dy + (float)(ho + i);
        float px = dx + (float)(wo + j);
        float y0f = floorf(py), x0f = floorf(px);
        float ly = py - y0f, lx = px - x0f;
        int y0 = (int)y0f, x0 = (int)x0f;
        int y1 = y0 + 1,  x1 = x0 + 1;

        float my0 = (y0 >= 0 && y0 < 130) ? 1.f : 0.f;
        float my1 = (y1 >= 0 && y1 < 130) ? 1.f : 0.f;
        float mx0 = (x0 >= 0 && x0 < 130) ? 1.f : 0.f;
        float mx1 = (x1 >= 0 && x1 < 130) ? 1.f : 0.f;

        int yc0 = min(max(y0, 0), 129), yc1 = min(max(y1, 0), 129);
        int xc0 = min(max(x0, 0), 129), xc1 = min(max(x1, 0), 129);

        float a00 = (1.f-ly)*(1.f-lx)*my0*mx0;
        float a01 = (1.f-ly)*lx      *my0*mx1;
        float a10 = ly      *(1.f-lx)*my1*mx0;
        float a11 = ly      *lx      *my1*mx1;

        int i00 = yc0*130 + xc0, i01 = yc0*130 + xc1;
        int i10 = yc1*130 + xc0, i11 = yc1*130 + xc1;

        const float* xb = x + ((size_t)b*64 + g*8)*16900;
        int kbase = (g*8)*9 + tap;
#pragma unroll
        for (int c = 0; c < 8; ++c) {
            const float* xc = xb + c*16900;
            float v = a00*xc[i00] + a01*xc[i01] + a10*xc[i10] + a11*xc[i11];
            v_s[(kbase + c*9)*32 + pix] = v;
        }
    }

    // ---- Phase 2: y[co][pix] = sum_k v_s[k][pix] * wdt[k][co]
    // 256 threads = 32 pixels x 8 cout-groups (8 couts each), f32x2 pairs.
    int pix = tid & 31, cg = tid >> 5;    // cg 0..7 -> couts cg*8..cg*8+7
    u64 acc[4];
#pragma unroll
    for (int i = 0; i < 4; ++i) acc[i] = 0ull;

    for (int kc = 0; kc < 9; ++kc) {      // 9 chunks of 64 k
        CP_WAIT0();
        __syncthreads();                  // chunk ready + (kc>0) prev buffer free
        const float* wb = wd_s + (kc & 1)*4096;
        if (kc < 8) {
            float* wn = wd_s + ((kc+1) & 1)*4096;
            const float* gsrc = g_wdt + (kc+1)*4096;
            for (int i = tid; i < 1024; i += 256) cp16(wn + i*4, gsrc + i*4);
            CP_COMMIT();
        }
#pragma unroll
        for (int kk = 0; kk < 64; ++kk) {
            float xv = v_s[(kc*64 + kk)*32 + pix];
            u64 xv2 = pack2(xv, xv);
            const ulonglong2* wp = (const ulonglong2*)(wb + kk*64 + cg*8);
            ulonglong2 wA = wp[0], wB = wp[1];
            fma2(acc[0], xv2, wA.x); fma2(acc[1], xv2, wA.y);
            fma2(acc[2], xv2, wB.x); fma2(acc[3], xv2, wB.y);
        }
    }

    float* yb = yout + ((size_t)b*64 + cg*8)*16384 + (size_t)ho*128 + wo0 + pix;
#pragma unroll
    for (int q = 0; q < 4; ++q) {
        yb[(size_t)(2*q)  *16384] = lo32(acc[q]);
        yb[(size_t)(2*q+1)*16384] = hi32(acc[q]);
    }
}

// ---------------------------------------------------------------------------
extern "C" void kernel_launch(void* const* d_in, const int* in_sizes, int n_in,
                              void* d_out, int out_size) {
    const float* x  = (const float*)d_in[0];
    const float* w1 = (const float*)d_in[1];
    const float* b1 = (const float*)d_in[2];
    const float* w2 = (const float*)d_in[3];
    const float* b2 = (const float*)d_in[4];
    const float* wd = (const float*)d_in[5];

    float* out    = (float*)d_out;
    float* yout   = out;              // y:  [16,64,128,128]
    float* offout = out + YSIZE_;     // off:[16,144,128,128]

    const int DEFORM_SMEM = (576*32 + 2*64*64) * 4;   // 106496 B
    cudaFuncSetAttribute(deform_kernel,
                         cudaFuncAttributeMaxDynamicSharedMemorySize, DEFORM_SMEM);

    prep_kernel<<<324, 256>>>(w1, w2, wd);
    conv1_kernel<<<dim3(4, 8, 64), 256>>>(x, b1);
    conv2_kernel<<<4096, 256>>>(b2, offout);
    deform_kernel<<<dim3(4, 128, 16), 256, DEFORM_SMEM>>>(x, offout, yout);
}